// round 4
// baseline (speedup 1.0000x reference)
#include <cuda_runtime.h>
#include <cstdint>

#define NN   2048
#define NE   4096
#define NG   32
#define AD   79
#define BD   12
#define DD   128
#define NL   6
#define NT   6
#define KKD  16512          // 128*128 + 128 bias rows
#define KSPL 8
#define KLEN 2064           // KKD / KSPL
#define EMAX 96

typedef unsigned long long ull;

// ------------- static scratch (no allocations allowed) -------------
__device__ float g_h[NN * DD];
__device__ float g_t[NE * DD];
__device__ float g_S[(size_t)NN * KKD];            // 135 MB
__device__ float g_W2T[(size_t)NL * KKD * DD];     // 50.7 MB
__device__ float g_part[(size_t)KSPL * NN * DD];
__device__ float g_agg[NN * DD];
__device__ float g_gi[NN * 384];
__device__ float g_gh[NN * 384];
__device__ float g_WihT[NL * 128 * 384];
__device__ float g_WhhT[NL * 128 * 384];
__device__ float g_lWihT[128 * 512];
__device__ float g_lWhhT[128 * 512];
__device__ int   g_src[NE], g_dst[NE];
__device__ int   g_eidx[NN * EMAX];
__device__ int   g_cnt[NN];

// ------------- helpers -------------
__device__ __forceinline__ float gelu_f(float x) {
    return 0.5f * x * (1.0f + erff(x * 0.70710678f));
}
__device__ __forceinline__ float sigm(float x) { return 1.0f / (1.0f + expf(-x)); }

__device__ __forceinline__ ull pk2(float lo, float hi) {
    ull r; asm("mov.b64 %0, {%1, %2};" : "=l"(r) : "f"(lo), "f"(hi)); return r;
}
__device__ __forceinline__ void upk2(ull v, float& lo, float& hi) {
    asm("mov.b64 {%0, %1}, %2;" : "=f"(lo), "=f"(hi) : "l"(v));
}
__device__ __forceinline__ void ffma2(ull& d, ull a, ull b) {
    asm("fma.rn.f32x2 %0, %1, %2, %0;" : "+l"(d) : "l"(a), "l"(b));
}

__device__ __forceinline__ float bsum128(float v, float* red) {
    #pragma unroll
    for (int o = 16; o > 0; o >>= 1) v += __shfl_down_sync(0xffffffffu, v, o);
    if ((threadIdx.x & 31) == 0) red[threadIdx.x >> 5] = v;
    __syncthreads();
    float r = red[0] + red[1] + red[2] + red[3];
    __syncthreads();
    return r;
}

// ------------- edge_index dtype normalize (int32 vs int64) -------------
__global__ void k_edgenorm(const int* __restrict__ ei) {
    bool is64 = true;
    for (int i = 0; i < 128; i++)
        if (ei[2 * i + 1] != 0) { is64 = false; break; }
    int e = blockIdx.x * blockDim.x + threadIdx.x;
    if (e < NE) {
        g_src[e] = is64 ? ei[2 * e]        : ei[e];
        g_dst[e] = is64 ? ei[2 * (NE + e)] : ei[NE + e];
    }
}

// ------------- per-node in-edge lists (deterministic order) -------------
__global__ void k_elist() {
    int n = blockIdx.x, t = threadIdx.x;
    int cnt = 0;
    for (int base = 0; base < NE; base += 32) {
        int e = base + t;
        bool ok = (g_dst[e] == n);
        unsigned m = __ballot_sync(0xffffffffu, ok);
        if (ok) {
            int pos = cnt + __popc(m & ((1u << t) - 1u));
            if (pos < EMAX) g_eidx[n * EMAX + pos] = e;
        }
        cnt += __popc(m);
    }
    if (t == 0) g_cnt[n] = cnt > EMAX ? EMAX : cnt;
}

// ------------- W2 transpose: W2T[l][k*128+j][i] = eW2[l][k][i*128+j] -------------
__global__ void k_transpose(const float* __restrict__ eW2, const float* __restrict__ eb2) {
    int kk = blockIdx.x, l = blockIdx.y, t = threadIdx.x;  // 256 thr
    const float* src = (kk < 128) ? (eW2 + ((size_t)l * 128 + kk) * 16384)
                                  : (eb2 + (size_t)l * 16384);
    float* dst = g_W2T + (size_t)l * KKD * DD + (size_t)kk * 128 * 128;
    __shared__ float s[32][129];
    for (int i0 = 0; i0 < 128; i0 += 32) {
        for (int q = t; q < 32 * 128; q += 256) {
            int ii = q >> 7, j = q & 127;
            s[ii][j] = src[(i0 + ii) * 128 + j];
        }
        __syncthreads();
        for (int q = t; q < 32 * 128; q += 256) {
            int j = q >> 5, c = q & 31;
            dst[j * 128 + i0 + c] = s[c][j];
        }
        __syncthreads();
    }
}

// ------------- small transpose: B[l][c][r] = A[l][r][c] -------------
__global__ void k_tr3(const float* __restrict__ A, float* __restrict__ B,
                      int L, int R, int C) {
    size_t tot = (size_t)L * R * C;
    for (size_t idx = blockIdx.x * (size_t)blockDim.x + threadIdx.x; idx < tot;
         idx += (size_t)gridDim.x * blockDim.x) {
        int c = (int)(idx % C);
        size_t tmp = idx / C;
        int r = (int)(tmp % R);
        int l = (int)(tmp / R);
        B[((size_t)l * C + c) * R + r] = A[idx];
    }
}

// ------------- atom embedding: gelu(LN(x@W + b)) -------------
__global__ void k_embed(const float* __restrict__ x, const float* __restrict__ W,
                        const float* __restrict__ b, const float* __restrict__ lg,
                        const float* __restrict__ lb) {
    int n = blockIdx.x, t = threadIdx.x;
    __shared__ float sx[AD];
    __shared__ float red[4];
    if (t < AD) sx[t] = x[n * AD + t];
    __syncthreads();
    float acc = b[t];
    for (int a = 0; a < AD; a++) acc += sx[a] * W[a * DD + t];
    float mu  = bsum128(acc, red) * (1.0f / DD);
    float d   = acc - mu;
    float var = bsum128(d * d, red) * (1.0f / DD);
    float y   = d * rsqrtf(var + 1e-5f) * lg[t] + lb[t];
    g_h[n * DD + t] = gelu_f(y);
}

// ------------- edge hidden: t = gelu(ea @ eW1 + eb1) -------------
__global__ void k_edget(const float* __restrict__ ea, const float* __restrict__ W1,
                        const float* __restrict__ b1) {
    int e = blockIdx.x, t = threadIdx.x;
    __shared__ float sa[BD];
    if (t < BD) sa[t] = ea[e * BD + t];
    __syncthreads();
    float acc = b1[t];
    #pragma unroll
    for (int a = 0; a < BD; a++) acc += sa[a] * W1[a * DD + t];
    g_t[e * DD + t] = gelu_f(acc);
}

// ------------- S build: S[n, k*128+j] = sum_{e->n} t[e,k]*h[src,j]; bias row = hsum -------------
__global__ void __launch_bounds__(128) k_sbuild() {
    int n = blockIdx.x, half = blockIdx.y, t = threadIdx.x;
    __shared__ float st[64];
    float a[64];
    #pragma unroll
    for (int i = 0; i < 64; i++) a[i] = 0.0f;
    float hs = 0.0f;
    int cnt = g_cnt[n];
    for (int m = 0; m < cnt; m++) {
        int e = g_eidx[n * EMAX + m];
        int s = g_src[e];
        float hv = g_h[s * DD + t];
        if (t < 64) st[t] = g_t[e * DD + half * 64 + t];
        __syncthreads();
        #pragma unroll
        for (int i = 0; i < 64; i++) a[i] += st[i] * hv;
        hs += hv;
        __syncthreads();
    }
    float* Sr = g_S + (size_t)n * KKD + half * 64 * DD;
    #pragma unroll
    for (int i = 0; i < 64; i++) Sr[(size_t)i * DD + t] = a[i];
    if (half == 1) g_S[(size_t)n * KKD + 16384 + t] = hs;
}

// ------------- SGEMM: C[split] = A[M x K-chunk] * B[K x N], FFMA2 inner -------------
// block: 64(M) x 128(N) tile, 256 threads, thread = 8m x 4n
__global__ void __launch_bounds__(256) k_gemm(
    const float* __restrict__ A, int lda,
    const float* __restrict__ B, int ldb,
    float* __restrict__ C, int ldc, size_t splitStride, int Klen)
{
    __shared__ float As[8][64];
    __shared__ float Bs[8][128];
    int tid = threadIdx.x;
    int tm = tid >> 5, tn = tid & 31;
    int m0 = blockIdx.x * 64, n0 = blockIdx.y * 128;
    int k0 = blockIdx.z * Klen;
    ull c2[8][2];
    #pragma unroll
    for (int mm = 0; mm < 8; mm++) { c2[mm][0] = 0ull; c2[mm][1] = 0ull; }

    for (int kt = 0; kt < Klen; kt += 8) {
        int k = k0 + kt;
        #pragma unroll
        for (int q = 0; q < 2; q++) {
            int idx = tid * 2 + q;
            int m = idx >> 3, kk = idx & 7;
            As[kk][m] = A[(size_t)(m0 + m) * lda + k + kk];
        }
        #pragma unroll
        for (int q = 0; q < 4; q++) {
            int idx = tid + q * 256;
            int kk = idx >> 7, n = idx & 127;
            Bs[kk][n] = B[(size_t)(k + kk) * ldb + n0 + n];
        }
        __syncthreads();
        #pragma unroll
        for (int kk = 0; kk < 8; kk++) {
            float4 a0 = *(float4*)&As[kk][tm * 8];
            float4 a1 = *(float4*)&As[kk][tm * 8 + 4];
            float4 b  = *(float4*)&Bs[kk][tn * 4];
            ull b0 = pk2(b.x, b.y), b1 = pk2(b.z, b.w);
            ffma2(c2[0][0], pk2(a0.x, a0.x), b0); ffma2(c2[0][1], pk2(a0.x, a0.x), b1);
            ffma2(c2[1][0], pk2(a0.y, a0.y), b0); ffma2(c2[1][1], pk2(a0.y, a0.y), b1);
            ffma2(c2[2][0], pk2(a0.z, a0.z), b0); ffma2(c2[2][1], pk2(a0.z, a0.z), b1);
            ffma2(c2[3][0], pk2(a0.w, a0.w), b0); ffma2(c2[3][1], pk2(a0.w, a0.w), b1);
            ffma2(c2[4][0], pk2(a1.x, a1.x), b0); ffma2(c2[4][1], pk2(a1.x, a1.x), b1);
            ffma2(c2[5][0], pk2(a1.y, a1.y), b0); ffma2(c2[5][1], pk2(a1.y, a1.y), b1);
            ffma2(c2[6][0], pk2(a1.z, a1.z), b0); ffma2(c2[6][1], pk2(a1.z, a1.z), b1);
            ffma2(c2[7][0], pk2(a1.w, a1.w), b0); ffma2(c2[7][1], pk2(a1.w, a1.w), b1);
        }
        __syncthreads();
    }
    float* Co = C + blockIdx.z * splitStride;
    #pragma unroll
    for (int mm = 0; mm < 8; mm++) {
        float4 o;
        upk2(c2[mm][0], o.x, o.y);
        upk2(c2[mm][1], o.z, o.w);
        *(float4*)&Co[(size_t)(m0 + tm * 8 + mm) * ldc + n0 + tn * 4] = o;
    }
}

// ------------- reduce split-K partials (fixed order: deterministic) -------------
__global__ void k_reduce() {
    int i = blockIdx.x * blockDim.x + threadIdx.x;   // 512x512 = 262144
    float s = 0.0f;
    #pragma unroll
    for (int p = 0; p < KSPL; p++) s += g_part[(size_t)p * NN * DD + i];
    g_agg[i] = s;
}

// ------------- GRU elementwise + LN + residual -------------
__global__ void k_gru(const float* __restrict__ bih, const float* __restrict__ bhh,
                      const float* __restrict__ lg, const float* __restrict__ lb) {
    int n = blockIdx.x, t = threadIdx.x;
    __shared__ float red[4];
    float ir  = g_gi[n * 384 + t]       + bih[t];
    float iz  = g_gi[n * 384 + 128 + t] + bih[128 + t];
    float inn = g_gi[n * 384 + 256 + t] + bih[256 + t];
    float hr  = g_gh[n * 384 + t]       + bhh[t];
    float hz  = g_gh[n * 384 + 128 + t] + bhh[128 + t];
    float hn  = g_gh[n * 384 + 256 + t] + bhh[256 + t];
    float r = sigm(ir + hr);
    float z = sigm(iz + hz);
    float nn = tanhf(inn + r * hn);
    float hold = g_h[n * DD + t];
    float hnew = (1.0f - z) * nn + z * hold;
    float mu  = bsum128(hnew, red) * (1.0f / DD);
    float d   = hnew - mu;
    float var = bsum128(d * d, red) * (1.0f / DD);
    g_h[n * DD + t] = d * rsqrtf(var + 1e-5f) * lg[t] + lb[t] + hold;
}

// ------------- Set2Set (6 iters) + shared MLP + heads, one block per graph -------------
__global__ void __launch_bounds__(128) k_s2s(
    const float* __restrict__ lbih, const float* __restrict__ lbhh,
    const float* __restrict__ Wsh, const float* __restrict__ bsh,
    const float* __restrict__ Whd, const float* __restrict__ bhd,
    float* __restrict__ out)
{
    int g = blockIdx.x, t = threadIdx.x;
    __shared__ float hl[64 * 129];
    __shared__ float hg[128], cg[128], ro[128], sc[64], w_s[64];
    __shared__ float qs[256], sh2[128];
    for (int q = t; q < 64 * 128; q += 128) {
        int nn = q >> 7, i = q & 127;
        hl[nn * 129 + i] = g_h[(g * 64 + nn) * 128 + i];
    }
    hg[t] = 0.0f; cg[t] = 0.0f;
    __syncthreads();

    for (int it = 0; it < 6; it++) {
        if (t < 64) {
            float s = 0.0f;
            for (int i = 0; i < 128; i++) s += hl[t * 129 + i] * hg[i];
            sc[t] = s;
        }
        __syncthreads();
        if (t == 0) {
            float m = 0.0f;
            for (int nn = 0; nn < 64; nn++) m = fmaxf(m, sc[nn]);
            float ss = 0.0f;
            for (int nn = 0; nn < 64; nn++) { float e = expf(sc[nn] - m); w_s[nn] = e; ss += e; }
            float inv = 1.0f / (ss + 1e-8f);
            for (int nn = 0; nn < 64; nn++) w_s[nn] *= inv;
        }
        __syncthreads();
        {
            float r = 0.0f;
            for (int nn = 0; nn < 64; nn++) r += hl[nn * 129 + t] * w_s[nn];
            ro[t] = r;
        }
        __syncthreads();
        float ga[4];
        #pragma unroll
        for (int qg = 0; qg < 4; qg++) ga[qg] = lbih[qg * 128 + t] + lbhh[qg * 128 + t];
        for (int j = 0; j < 128; j++) {
            float rj = ro[j], hj = hg[j];
            #pragma unroll
            for (int qg = 0; qg < 4; qg++)
                ga[qg] += rj * g_lWihT[j * 512 + qg * 128 + t]
                        + hj * g_lWhhT[j * 512 + qg * 128 + t];
        }
        float cn = sigm(ga[1]) * cg[t] + sigm(ga[0]) * tanhf(ga[2]);
        float hn = sigm(ga[3]) * tanhf(cn);
        __syncthreads();
        hg[t] = hn; cg[t] = cn;
        __syncthreads();
    }
    qs[t] = hg[t]; qs[128 + t] = ro[t];
    __syncthreads();
    float acc = bsh[t];
    for (int j = 0; j < 256; j++) acc += qs[j] * Wsh[j * 128 + t];
    sh2[t] = gelu_f(acc);
    __syncthreads();
    if (t < NT) {
        float o = bhd[t];
        for (int i = 0; i < 128; i++) o += sh2[i] * Whd[i * NT + t];
        out[g * NT + t] = o;
    }
}

// ------------- launch -------------
extern "C" void kernel_launch(void* const* d_in, const int* in_sizes, int n_in,
                              void* d_out, int out_size) {
    const float* x        = (const float*)d_in[0];
    const int*   ei       = (const int*)  d_in[1];
    const float* ea       = (const float*)d_in[2];
    const float* W_embed  = (const float*)d_in[4];
    const float* b_embed  = (const float*)d_in[5];
    const float* ln_eg    = (const float*)d_in[6];
    const float* ln_eb    = (const float*)d_in[7];
    const float* eW1      = (const float*)d_in[8];
    const float* eb1      = (const float*)d_in[9];
    const float* eW2      = (const float*)d_in[10];
    const float* eb2      = (const float*)d_in[11];
    const float* gWih     = (const float*)d_in[12];
    const float* gWhh     = (const float*)d_in[13];
    const float* gbih     = (const float*)d_in[14];
    const float* gbhh     = (const float*)d_in[15];
    const float* lng      = (const float*)d_in[16];
    const float* lnb      = (const float*)d_in[17];
    const float* lWih     = (const float*)d_in[18];
    const float* lWhh     = (const float*)d_in[19];
    const float* lbih     = (const float*)d_in[20];
    const float* lbhh     = (const float*)d_in[21];
    const float* Wsh      = (const float*)d_in[22];
    const float* bsh      = (const float*)d_in[23];
    const float* Whd      = (const float*)d_in[24];
    const float* bhd      = (const float*)d_in[25];
    float* out = (float*)d_out;

    float* dW2T; cudaGetSymbolAddress((void**)&dW2T, g_W2T);
    float* dWihT; cudaGetSymbolAddress((void**)&dWihT, g_WihT);
    float* dWhhT; cudaGetSymbolAddress((void**)&dWhhT, g_WhhT);
    float* dlWihT; cudaGetSymbolAddress((void**)&dlWihT, g_lWihT);
    float* dlWhhT; cudaGetSymbolAddress((void**)&dlWhhT, g_lWhhT);
    float* dS; cudaGetSymbolAddress((void**)&dS, g_S);
    float* dPart; cudaGetSymbolAddress((void**)&dPart, g_part);
    float* dAgg; cudaGetSymbolAddress((void**)&dAgg, g_agg);
    float* dGi; cudaGetSymbolAddress((void**)&dGi, g_gi);
    float* dGh; cudaGetSymbolAddress((void**)&dGh, g_gh);
    float* dH; cudaGetSymbolAddress((void**)&dH, g_h);

    k_edgenorm<<<(NE + 127) / 128, 128>>>(ei);
    k_elist<<<NN, 32>>>();
    k_transpose<<<dim3(129, NL), 256>>>(eW2, eb2);
    k_tr3<<<256, 256>>>(gWih, dWihT, NL, 384, 128);
    k_tr3<<<256, 256>>>(gWhh, dWhhT, NL, 384, 128);
    k_tr3<<<64, 256>>>(lWih, dlWihT, 1, 512, 128);
    k_tr3<<<64, 256>>>(lWhh, dlWhhT, 1, 512, 128);
    k_embed<<<NN, 128>>>(x, W_embed, b_embed, ln_eg, ln_eb);

    for (int l = 0; l < NL; l++) {
        k_edget<<<NE, 128>>>(ea, eW1 + (size_t)l * BD * DD, eb1 + l * DD);
        k_sbuild<<<dim3(NN, 2), 128>>>();
        k_gemm<<<dim3(32, 1, KSPL), 256>>>(dS, KKD,
                                           dW2T + (size_t)l * KKD * DD, 128,
                                           dPart, 128, (size_t)NN * DD, KLEN);
        k_reduce<<<512, 512>>>();
        k_gemm<<<dim3(32, 3, 1), 256>>>(dAgg, 128,
                                        dWihT + (size_t)l * 128 * 384, 384,
                                        dGi, 384, 0, 128);
        k_gemm<<<dim3(32, 3, 1), 256>>>(dH, 128,
                                        dWhhT + (size_t)l * 128 * 384, 384,
                                        dGh, 384, 0, 128);
        k_gru<<<NN, 128>>>(gbih + l * 384, gbhh + l * 384, lng + l * DD, lnb + l * DD);
    }
    k_s2s<<<NG, 128>>>(lbih, lbhh, Wsh, bsh, Whd, bhd, out);
}

// round 5
// speedup vs baseline: 1.3271x; 1.3271x over previous
#include <cuda_runtime.h>
#include <cstdint>

#define NN   2048
#define NE   4096
#define NG   32
#define AD   79
#define BD   12
#define DD   128
#define NL   6
#define NT   6
#define KKD  16512          // 128*128 + 128 bias rows
#define KSPL 16
#define KLEN 1032           // KKD / KSPL
#define EMAX 96

typedef unsigned long long ull;

// ------------- static scratch (no allocations allowed) -------------
__device__ float g_h[NN * DD];
__device__ float g_t[NE * DD];
__device__ float g_S[(size_t)NN * KKD];            // 135 MB
__device__ float g_W2T[(size_t)NL * KKD * DD];     // 50.7 MB
__device__ float g_part[(size_t)KSPL * NN * DD];   // 16 MB
__device__ float g_agg[NN * DD];
__device__ float g_gi[NN * 384];
__device__ float g_gh[NN * 384];
__device__ float g_WihT[NL * 128 * 384];
__device__ float g_WhhT[NL * 128 * 384];
__device__ float g_lWihT[128 * 512];
__device__ float g_lWhhT[128 * 512];
__device__ int   g_src[NE], g_dst[NE];
__device__ int   g_eidx[NN * EMAX];
__device__ int   g_cnt[NN];

// ------------- helpers -------------
__device__ __forceinline__ float gelu_f(float x) {
    return 0.5f * x * (1.0f + erff(x * 0.70710678f));
}
__device__ __forceinline__ float sigm(float x) { return 1.0f / (1.0f + expf(-x)); }

__device__ __forceinline__ ull pk2(float lo, float hi) {
    ull r; asm("mov.b64 %0, {%1, %2};" : "=l"(r) : "f"(lo), "f"(hi)); return r;
}
__device__ __forceinline__ void upk2(ull v, float& lo, float& hi) {
    asm("mov.b64 {%0, %1}, %2;" : "=f"(lo), "=f"(hi) : "l"(v));
}
__device__ __forceinline__ void ffma2(ull& d, ull a, ull b) {
    asm("fma.rn.f32x2 %0, %1, %2, %0;" : "+l"(d) : "l"(a), "l"(b));
}

__device__ __forceinline__ float bsum128(float v, float* red) {
    #pragma unroll
    for (int o = 16; o > 0; o >>= 1) v += __shfl_down_sync(0xffffffffu, v, o);
    if ((threadIdx.x & 31) == 0) red[threadIdx.x >> 5] = v;
    __syncthreads();
    float r = red[0] + red[1] + red[2] + red[3];
    __syncthreads();
    return r;
}

// ------------- prep: edge_index dtype normalize + per-node in-edge lists -------------
__global__ void k_prep(const int* __restrict__ ei) {
    int n = blockIdx.x, t = threadIdx.x;           // grid NN, 32 threads
    bool my64 = true;
    for (int i = t; i < 128; i += 32)
        if (ei[2 * i + 1] != 0) my64 = false;
    bool is64 = __all_sync(0xffffffffu, my64);
    if (t < 2) {                                   // fill src/dst slice (2 edges/block)
        int e = n * 2 + t;
        g_src[e] = is64 ? ei[2 * e]        : ei[e];
        g_dst[e] = is64 ? ei[2 * (NE + e)] : ei[NE + e];
    }
    int cnt = 0;
    for (int base = 0; base < NE; base += 32) {
        int e = base + t;
        int dv = is64 ? ei[2 * (NE + e)] : ei[NE + e];
        bool ok = (dv == n);
        unsigned m = __ballot_sync(0xffffffffu, ok);
        if (ok) {
            int pos = cnt + __popc(m & ((1u << t) - 1u));
            if (pos < EMAX) g_eidx[n * EMAX + pos] = e;
        }
        cnt += __popc(m);
    }
    if (t == 0) g_cnt[n] = cnt > EMAX ? EMAX : cnt;
}

// ------------- W2 transpose: W2T[l][k*128+j][i] = eW2[l][k][i*128+j] -------------
__global__ void k_transpose(const float* __restrict__ eW2, const float* __restrict__ eb2) {
    int kk = blockIdx.x, l = blockIdx.y, t = threadIdx.x;  // 256 thr
    const float* src = (kk < 128) ? (eW2 + ((size_t)l * 128 + kk) * 16384)
                                  : (eb2 + (size_t)l * 16384);
    float* dst = g_W2T + (size_t)l * KKD * DD + (size_t)kk * 128 * 128;
    __shared__ float s[32][129];
    for (int i0 = 0; i0 < 128; i0 += 32) {
        for (int q = t; q < 32 * 128; q += 256) {
            int ii = q >> 7, j = q & 127;
            s[ii][j] = src[(i0 + ii) * 128 + j];
        }
        __syncthreads();
        for (int q = t; q < 32 * 128; q += 256) {
            int j = q >> 5, c = q & 31;
            dst[j * 128 + i0 + c] = s[c][j];
        }
        __syncthreads();
    }
}

// ------------- small transpose: B[l][c][r] = A[l][r][c] -------------
__global__ void k_tr3(const float* __restrict__ A, float* __restrict__ B,
                      int L, int R, int C) {
    size_t tot = (size_t)L * R * C;
    for (size_t idx = blockIdx.x * (size_t)blockDim.x + threadIdx.x; idx < tot;
         idx += (size_t)gridDim.x * blockDim.x) {
        int c = (int)(idx % C);
        size_t tmp = idx / C;
        int r = (int)(tmp % R);
        int l = (int)(tmp / R);
        B[((size_t)l * C + c) * R + r] = A[idx];
    }
}

// ------------- atom embedding: gelu(LN(x@W + b)) -------------
__global__ void k_embed(const float* __restrict__ x, const float* __restrict__ W,
                        const float* __restrict__ b, const float* __restrict__ lg,
                        const float* __restrict__ lb) {
    int n = blockIdx.x, t = threadIdx.x;
    __shared__ float sx[AD];
    __shared__ float red[4];
    if (t < AD) sx[t] = x[n * AD + t];
    __syncthreads();
    float acc = b[t];
    for (int a = 0; a < AD; a++) acc += sx[a] * W[a * DD + t];
    float mu  = bsum128(acc, red) * (1.0f / DD);
    float d   = acc - mu;
    float var = bsum128(d * d, red) * (1.0f / DD);
    float y   = d * rsqrtf(var + 1e-5f) * lg[t] + lb[t];
    g_h[n * DD + t] = gelu_f(y);
}

// ------------- edge hidden: t = gelu(ea @ eW1 + eb1) -------------
__global__ void k_edget(const float* __restrict__ ea, const float* __restrict__ W1,
                        const float* __restrict__ b1) {
    int e = blockIdx.x, t = threadIdx.x;
    __shared__ float sa[BD];
    if (t < BD) sa[t] = ea[e * BD + t];
    __syncthreads();
    float acc = b1[t];
    #pragma unroll
    for (int a = 0; a < BD; a++) acc += sa[a] * W1[a * DD + t];
    g_t[e * DD + t] = gelu_f(acc);
}

// ------------- S build: S[n, k*128+j] = sum_{e->n} t[e,k]*h[src,j]; bias row = hsum -------------
__global__ void __launch_bounds__(128) k_sbuild() {
    int n = blockIdx.x, half = blockIdx.y, t = threadIdx.x;
    __shared__ float st[64];
    float a[64];
    #pragma unroll
    for (int i = 0; i < 64; i++) a[i] = 0.0f;
    float hs = 0.0f;
    int cnt = g_cnt[n];
    for (int m = 0; m < cnt; m++) {
        int e = g_eidx[n * EMAX + m];
        int s = g_src[e];
        float hv = g_h[s * DD + t];
        if (t < 64) st[t] = g_t[e * DD + half * 64 + t];
        __syncthreads();
        #pragma unroll
        for (int i = 0; i < 64; i++) a[i] += st[i] * hv;
        hs += hv;
        __syncthreads();
    }
    float* Sr = g_S + (size_t)n * KKD + half * 64 * DD;
    #pragma unroll
    for (int i = 0; i < 64; i++) Sr[(size_t)i * DD + t] = a[i];
    if (half == 1) g_S[(size_t)n * KKD + 16384 + t] = hs;
}

// ------------- SGEMM 128x128 tile, double-buffered, FFMA2, 8x8/thread -------------
__global__ void __launch_bounds__(256, 2) k_gemm(
    const float* __restrict__ A, int lda,
    const float* __restrict__ B, int ldb,
    float* __restrict__ C, int ldc, size_t splitStride, int Klen)
{
    __shared__ float As[2][8][132];
    __shared__ float Bs[2][8][128];
    int tid = threadIdx.x;
    int w = tid >> 5, l = tid & 31;
    int wm = w & 3, wn = w >> 2;           // 4x2 warp grid
    int lm = l & 3, ln = l >> 2;           // 4x8 lane grid
    int row = wm * 32 + lm * 8;
    int col = wn * 64 + ln * 8;
    int m0 = blockIdx.x * 128, n0 = blockIdx.y * 128;
    int k0 = blockIdx.z * Klen;

    int am = tid >> 1, ak = (tid & 1) * 4;     // A: 2 thr/row, float4 along k
    int bk = tid >> 5, bn = (tid & 31) * 4;    // B: 1 warp/row, float4 along n

    const float* Aptr = A + (size_t)(m0 + am) * lda + k0 + ak;
    const float* Bptr = B + (size_t)(k0 + bk) * ldb + n0 + bn;

    ull acc[8][4];
    #pragma unroll
    for (int mm = 0; mm < 8; mm++)
        #pragma unroll
        for (int nn = 0; nn < 4; nn++) acc[mm][nn] = 0ull;

    int ntiles = Klen >> 3;
    float4 ra = *(const float4*)Aptr;
    float4 rb = *(const float4*)Bptr;
    As[0][ak + 0][am] = ra.x; As[0][ak + 1][am] = ra.y;
    As[0][ak + 2][am] = ra.z; As[0][ak + 3][am] = ra.w;
    *(float4*)&Bs[0][bk][bn] = rb;
    __syncthreads();

    for (int t = 0; t < ntiles; t++) {
        int cur = t & 1, nxt = cur ^ 1;
        if (t + 1 < ntiles) {
            ra = *(const float4*)(Aptr + (t + 1) * 8);
            rb = *(const float4*)(Bptr + (size_t)(t + 1) * 8 * ldb);
        }
        #pragma unroll
        for (int kk = 0; kk < 8; kk++) {
            float4 a0 = *(float4*)&As[cur][kk][row];
            float4 a1 = *(float4*)&As[cur][kk][row + 4];
            float4 b0 = *(float4*)&Bs[cur][kk][col];
            float4 b1 = *(float4*)&Bs[cur][kk][col + 4];
            ull bp0 = pk2(b0.x, b0.y), bp1 = pk2(b0.z, b0.w);
            ull bp2 = pk2(b1.x, b1.y), bp3 = pk2(b1.z, b1.w);
            float av[8] = {a0.x, a0.y, a0.z, a0.w, a1.x, a1.y, a1.z, a1.w};
            #pragma unroll
            for (int mm = 0; mm < 8; mm++) {
                ull ap = pk2(av[mm], av[mm]);
                ffma2(acc[mm][0], ap, bp0);
                ffma2(acc[mm][1], ap, bp1);
                ffma2(acc[mm][2], ap, bp2);
                ffma2(acc[mm][3], ap, bp3);
            }
        }
        if (t + 1 < ntiles) {
            As[nxt][ak + 0][am] = ra.x; As[nxt][ak + 1][am] = ra.y;
            As[nxt][ak + 2][am] = ra.z; As[nxt][ak + 3][am] = ra.w;
            *(float4*)&Bs[nxt][bk][bn] = rb;
        }
        __syncthreads();
    }

    float* Co = C + blockIdx.z * splitStride;
    #pragma unroll
    for (int mm = 0; mm < 8; mm++) {
        float4 o0, o1;
        upk2(acc[mm][0], o0.x, o0.y); upk2(acc[mm][1], o0.z, o0.w);
        upk2(acc[mm][2], o1.x, o1.y); upk2(acc[mm][3], o1.z, o1.w);
        size_t base = (size_t)(m0 + row + mm) * ldc + n0 + col;
        *(float4*)&Co[base]     = o0;
        *(float4*)&Co[base + 4] = o1;
    }
}

// ------------- reduce split-K partials (fixed order, float4) -------------
__global__ void k_reduce() {
    int i = blockIdx.x * blockDim.x + threadIdx.x;   // 65536 float4s
    const float4* p = (const float4*)g_part;
    float4 s = {0.f, 0.f, 0.f, 0.f};
    #pragma unroll
    for (int q = 0; q < KSPL; q++) {
        float4 v = p[(size_t)q * (NN * DD / 4) + i];
        s.x += v.x; s.y += v.y; s.z += v.z; s.w += v.w;
    }
    ((float4*)g_agg)[i] = s;
}

// ------------- GRU elementwise + LN + residual -------------
__global__ void k_gru(const float* __restrict__ bih, const float* __restrict__ bhh,
                      const float* __restrict__ lg, const float* __restrict__ lb) {
    int n = blockIdx.x, t = threadIdx.x;
    __shared__ float red[4];
    float ir  = g_gi[n * 384 + t]       + bih[t];
    float iz  = g_gi[n * 384 + 128 + t] + bih[128 + t];
    float inn = g_gi[n * 384 + 256 + t] + bih[256 + t];
    float hr  = g_gh[n * 384 + t]       + bhh[t];
    float hz  = g_gh[n * 384 + 128 + t] + bhh[128 + t];
    float hn  = g_gh[n * 384 + 256 + t] + bhh[256 + t];
    float r = sigm(ir + hr);
    float z = sigm(iz + hz);
    float nn = tanhf(inn + r * hn);
    float hold = g_h[n * DD + t];
    float hnew = (1.0f - z) * nn + z * hold;
    float mu  = bsum128(hnew, red) * (1.0f / DD);
    float d   = hnew - mu;
    float var = bsum128(d * d, red) * (1.0f / DD);
    g_h[n * DD + t] = d * rsqrtf(var + 1e-5f) * lg[t] + lb[t] + hold;
}

// ------------- Set2Set (6 iters) + shared MLP + heads, one block per graph -------------
__global__ void __launch_bounds__(128) k_s2s(
    const float* __restrict__ lbih, const float* __restrict__ lbhh,
    const float* __restrict__ Wsh, const float* __restrict__ bsh,
    const float* __restrict__ Whd, const float* __restrict__ bhd,
    float* __restrict__ out)
{
    int g = blockIdx.x, t = threadIdx.x;
    __shared__ float hl[64 * 129];
    __shared__ float hg[128], cg[128], ro[128], sc[64], w_s[64];
    __shared__ float qs[256], sh2[128];
    for (int q = t; q < 64 * 128; q += 128) {
        int nn = q >> 7, i = q & 127;
        hl[nn * 129 + i] = g_h[(g * 64 + nn) * 128 + i];
    }
    hg[t] = 0.0f; cg[t] = 0.0f;
    __syncthreads();

    for (int it = 0; it < 6; it++) {
        if (t < 64) {
            float s = 0.0f;
            for (int i = 0; i < 128; i++) s += hl[t * 129 + i] * hg[i];
            sc[t] = s;
        }
        __syncthreads();
        if (t == 0) {
            float m = 0.0f;
            for (int nn = 0; nn < 64; nn++) m = fmaxf(m, sc[nn]);
            float ss = 0.0f;
            for (int nn = 0; nn < 64; nn++) { float e = expf(sc[nn] - m); w_s[nn] = e; ss += e; }
            float inv = 1.0f / (ss + 1e-8f);
            for (int nn = 0; nn < 64; nn++) w_s[nn] *= inv;
        }
        __syncthreads();
        {
            float r = 0.0f;
            for (int nn = 0; nn < 64; nn++) r += hl[nn * 129 + t] * w_s[nn];
            ro[t] = r;
        }
        __syncthreads();
        float ga[4];
        #pragma unroll
        for (int qg = 0; qg < 4; qg++) ga[qg] = lbih[qg * 128 + t] + lbhh[qg * 128 + t];
        for (int j = 0; j < 128; j++) {
            float rj = ro[j], hj = hg[j];
            #pragma unroll
            for (int qg = 0; qg < 4; qg++)
                ga[qg] += rj * g_lWihT[j * 512 + qg * 128 + t]
                        + hj * g_lWhhT[j * 512 + qg * 128 + t];
        }
        float cn = sigm(ga[1]) * cg[t] + sigm(ga[0]) * tanhf(ga[2]);
        float hn = sigm(ga[3]) * tanhf(cn);
        __syncthreads();
        hg[t] = hn; cg[t] = cn;
        __syncthreads();
    }
    qs[t] = hg[t]; qs[128 + t] = ro[t];
    __syncthreads();
    float acc = bsh[t];
    for (int j = 0; j < 256; j++) acc += qs[j] * Wsh[j * 128 + t];
    sh2[t] = gelu_f(acc);
    __syncthreads();
    if (t < NT) {
        float o = bhd[t];
        for (int i = 0; i < 128; i++) o += sh2[i] * Whd[i * NT + t];
        out[g * NT + t] = o;
    }
}

// ------------- launch -------------
extern "C" void kernel_launch(void* const* d_in, const int* in_sizes, int n_in,
                              void* d_out, int out_size) {
    const float* x        = (const float*)d_in[0];
    const int*   ei       = (const int*)  d_in[1];
    const float* ea       = (const float*)d_in[2];
    const float* W_embed  = (const float*)d_in[4];
    const float* b_embed  = (const float*)d_in[5];
    const float* ln_eg    = (const float*)d_in[6];
    const float* ln_eb    = (const float*)d_in[7];
    const float* eW1      = (const float*)d_in[8];
    const float* eb1      = (const float*)d_in[9];
    const float* eW2      = (const float*)d_in[10];
    const float* eb2      = (const float*)d_in[11];
    const float* gWih     = (const float*)d_in[12];
    const float* gWhh     = (const float*)d_in[13];
    const float* gbih     = (const float*)d_in[14];
    const float* gbhh     = (const float*)d_in[15];
    const float* lng      = (const float*)d_in[16];
    const float* lnb      = (const float*)d_in[17];
    const float* lWih     = (const float*)d_in[18];
    const float* lWhh     = (const float*)d_in[19];
    const float* lbih     = (const float*)d_in[20];
    const float* lbhh     = (const float*)d_in[21];
    const float* Wsh      = (const float*)d_in[22];
    const float* bsh      = (const float*)d_in[23];
    const float* Whd      = (const float*)d_in[24];
    const float* bhd      = (const float*)d_in[25];
    float* out = (float*)d_out;

    float* dW2T;  cudaGetSymbolAddress((void**)&dW2T, g_W2T);
    float* dWihT; cudaGetSymbolAddress((void**)&dWihT, g_WihT);
    float* dWhhT; cudaGetSymbolAddress((void**)&dWhhT, g_WhhT);
    float* dlWihT; cudaGetSymbolAddress((void**)&dlWihT, g_lWihT);
    float* dlWhhT; cudaGetSymbolAddress((void**)&dlWhhT, g_lWhhT);
    float* dS;    cudaGetSymbolAddress((void**)&dS, g_S);
    float* dPart; cudaGetSymbolAddress((void**)&dPart, g_part);
    float* dAgg;  cudaGetSymbolAddress((void**)&dAgg, g_agg);
    float* dGi;   cudaGetSymbolAddress((void**)&dGi, g_gi);
    float* dGh;   cudaGetSymbolAddress((void**)&dGh, g_gh);
    float* dH;    cudaGetSymbolAddress((void**)&dH, g_h);

    // launches 1..5, so launch #6 (ncu -s 5 -c 1) is the big GEMM
    k_prep<<<NN, 32>>>(ei);
    k_transpose<<<dim3(129, NL), 256>>>(eW2, eb2);
    k_embed<<<NN, 128>>>(x, W_embed, b_embed, ln_eg, ln_eb);

    for (int l = 0; l < NL; l++) {
        k_edget<<<NE, 128>>>(ea, eW1 + (size_t)l * BD * DD, eb1 + l * DD);
        k_sbuild<<<dim3(NN, 2), 128>>>();
        k_gemm<<<dim3(16, 1, KSPL), 256>>>(dS, KKD,
                                           dW2T + (size_t)l * KKD * DD, 128,
                                           dPart, 128, (size_t)NN * DD, KLEN);
        if (l == 0) {   // weight transposes: after 1st big GEMM (keeps it at launch #6)
            k_tr3<<<256, 256>>>(gWih, dWihT, NL, 384, 128);
            k_tr3<<<256, 256>>>(gWhh, dWhhT, NL, 384, 128);
            k_tr3<<<64, 256>>>(lWih, dlWihT, 1, 512, 128);
            k_tr3<<<64, 256>>>(lWhh, dlWhhT, 1, 512, 128);
        }
        k_reduce<<<128, 512>>>();
        k_gemm<<<dim3(16, 3, 1), 256>>>(dAgg, 128,
                                        dWihT + (size_t)l * 128 * 384, 384,
                                        dGi, 384, 0, 128);
        k_gemm<<<dim3(16, 3, 1), 256>>>(dH, 128,
                                        dWhhT + (size_t)l * 128 * 384, 384,
                                        dGh, 384, 0, 128);
        k_gru<<<NN, 128>>>(gbih + l * 384, gbhh + l * 384, lng + l * DD, lnb + l * DD);
    }
    k_s2s<<<NG, 128>>>(lbih, lbhh, Wsh, bsh, Whd, bhd, out);
}